// round 14
// baseline (speedup 1.0000x reference)
#include <cuda_runtime.h>
#include <cuda_fp16.h>
#include <math.h>

#define ECNT   300000
#define IECNT  300000
#define NENT   100000
#define NUSR   50000
#define DD     256
#define D4     64
#define EPSV   1e-8f
#define GAMMAV 0.2f

#define TILE   4096
#define EB     ((NENT + TILE - 1) / TILE)   // 25
#define UB     ((NUSR + TILE - 1) / TILE)   // 13

struct EdgeE { int tail; int rel; float alpha; float eta; };   // 16B
struct EdgeU { int item; float w; };                           // 8B

// ---------------- scratch (device globals; no allocations allowed) -----------
// Zero-invariant (cnt_e, cnt_u, seg_omega zero at k_count entry; seg_eta zero
// at k_alpha entry) is established by module load on call 1 and re-established
// every replay: k_count zeroes seg_eta, k_fillconv zeroes cnt/seg_omega.
__device__ int    g_cnt_e[NENT];
__device__ int    g_cnt_u[NUSR];
__device__ float  g_seg_omega[NENT];
__device__ float  g_seg_eta[NENT];
__device__ int    g_off_e[NENT + 1];
__device__ int    g_off_u[NUSR + 1];
__device__ int    g_cur_e[NENT];
__device__ int    g_cur_u[NUSR];
__device__ int    g_tilesum[EB + UB];
__device__ float  g_alpha[ECNT];
__device__ float  g_eta0[ECNT];
__device__ EdgeE  g_pe[ECNT];
__device__ EdgeU  g_pu[IECNT];
// fp16 entity states: [0],[1] = ping-pong hop states, [2] = fp16 copy of input
__device__ __half g_enth[3][NENT * DD];

// ---------------- helpers ----------------------------------------------------
__device__ __forceinline__ float cleanv(float v) {
    if (isnan(v)) return 0.0f;
    if (isinf(v)) return v > 0.f ? 10000.0f : 0.0001f;
    return v;
}

// ---------------- precompute --------------------------------------------------
// Also zeroes g_seg_eta (accumulated by the NEXT kernel, k_alpha) so no
// separate cleanup launch is needed.
__global__ void k_count(const int* __restrict__ head, const float* __restrict__ omega,
                        const int* __restrict__ iu) {
    int e = blockIdx.x * blockDim.x + threadIdx.x;
    if (e < NENT) g_seg_eta[e] = 0.f;
    if (e < ECNT) {
        int h = head[e];
        atomicAdd(&g_cnt_e[h], 1);
        atomicAdd(&g_seg_omega[h], omega[e]);
    }
    if (e < IECNT) {
        atomicAdd(&g_cnt_u[iu[e]], 1);
    }
}

__global__ void k_alpha(const int* __restrict__ head, const float* __restrict__ omega) {
    int e = blockIdx.x * blockDim.x + threadIdx.x;
    if (e < ECNT) {
        int h = head[e];
        float a = omega[e] / (g_seg_omega[h] + EPSV);
        g_alpha[e] = a;
        float e0 = (a > GAMMAV) ? a : 0.0f;
        g_eta0[e] = e0;
        atomicAdd(&g_seg_eta[h], e0);
    }
}

// Pass A: per-tile sums (38 independent blocks). Order-free, so reads are
// interleaved for perfect coalescing (cnt[tile + k*256 + t]).
__global__ void k_scanA() {
    int b = blockIdx.x;
    int which = (b >= EB);
    int tb = which ? b - EB : b;
    const int* cnt = which ? g_cnt_u : g_cnt_e;
    int n          = which ? NUSR    : NENT;
    int tbase = tb * TILE;
    int s = 0;
    #pragma unroll
    for (int k = 0; k < 16; k++) {
        int i = tbase + k * 256 + threadIdx.x;
        s += (i < n) ? cnt[i] : 0;
    }
    __shared__ int sh[8];
    int lane = threadIdx.x & 31, wid = threadIdx.x >> 5;
    #pragma unroll
    for (int o = 16; o > 0; o >>= 1) s += __shfl_down_sync(0xffffffffu, s, o);
    if (lane == 0) sh[wid] = s;
    __syncthreads();
    if (threadIdx.x == 0) {
        int t = 0;
        #pragma unroll
        for (int i = 0; i < 8; i++) t += sh[i];
        g_tilesum[b] = t;
    }
}

// Pass B+C merged: each block redundantly scans the tile sums of its segment,
// then re-scans its own tile with the global offset.
__global__ void k_scanBC() {
    int b = blockIdx.x;
    int which = (b >= EB);
    int tb = which ? b - EB : b;
    const int* cnt = which ? g_cnt_u : g_cnt_e;
    int* off       = which ? g_off_u : g_off_e;
    int* cur       = which ? g_cur_u : g_cur_e;
    int n          = which ? NUSR    : NENT;
    int nb         = which ? UB      : EB;
    int sbase      = which ? EB      : 0;

    __shared__ int s_tileoff;
    if (threadIdx.x < 32) {
        int lane = threadIdx.x;
        int v = (lane < nb) ? g_tilesum[sbase + lane] : 0;
        int x = v;
        #pragma unroll
        for (int o = 1; o < 32; o <<= 1) {
            int y = __shfl_up_sync(0xffffffffu, x, o);
            if (lane >= o) x += y;
        }
        if (lane == tb) s_tileoff = x - v;
    }
    __syncthreads();

    int t = threadIdx.x;
    int lane = t & 31, wid = t >> 5;
    int base = tb * TILE + t * 16;
    int v[16], loc = 0;
    #pragma unroll
    for (int k = 0; k < 16; k++) {
        int i = base + k;
        v[k] = (i < n) ? cnt[i] : 0;
        loc += v[k];
    }
    int x = loc;
    #pragma unroll
    for (int o = 1; o < 32; o <<= 1) {
        int y = __shfl_up_sync(0xffffffffu, x, o);
        if (lane >= o) x += y;
    }
    __shared__ int warpsum[8];
    if (lane == 31) warpsum[wid] = x;
    __syncthreads();
    int wpre = 0;
    #pragma unroll
    for (int i = 0; i < 8; i++) wpre += (i < wid) ? warpsum[i] : 0;
    int excl = s_tileoff + wpre + (x - loc);
    #pragma unroll
    for (int k = 0; k < 16; k++) {
        int i = base + k;
        if (i < n) { off[i] = excl; cur[i] = excl; }
        else if (i == n) { off[n] = excl; }
        excl += v[k];
    }
}

// CSR fill (packed payloads) + fp16 conversion of the input entity embedding.
// Also restores the zero-invariant for cnt_e / cnt_u / seg_omega (their last
// readers, k_scanBC / k_alpha, have already completed).
__global__ void k_fillconv(const int* __restrict__ head, const int* __restrict__ tail,
                           const int* __restrict__ etype,
                           const int* __restrict__ iu, const int* __restrict__ ii,
                           const float* __restrict__ w,
                           const float2* __restrict__ ent_in2) {
    int e = blockIdx.x * blockDim.x + threadIdx.x;
    if (e < ECNT) {
        int h = head[e];
        int pos = atomicAdd(&g_cur_e[h], 1);
        EdgeE ed;
        ed.tail  = tail[e];
        ed.rel   = etype[e] - 1;
        ed.alpha = g_alpha[e];
        ed.eta   = g_eta0[e] / (g_seg_eta[h] + EPSV);
        g_pe[pos] = ed;
    }
    if (e < IECNT) {
        int u = iu[e];
        int pos = atomicAdd(&g_cur_u[u], 1);
        EdgeU eu;
        eu.item = ii[e];
        eu.w    = w[e];
        g_pu[pos] = eu;
    }
    // restore zero-invariant for next replay
    if (e < NENT) { g_cnt_e[e] = 0; g_seg_omega[e] = 0.f; }
    if (e < NUSR) { g_cnt_u[e] = 0; }
    // fp16 copy of the input entity embedding (grid-stride)
    __half2* dst = (__half2*)g_enth[2];
    long total = (long)gridDim.x * blockDim.x;
    const long NH2 = (long)NENT * DD / 2;
    for (long i = e; i < NH2; i += total) {
        dst[i] = __float22half2_rn(ent_in2[i]);
    }
}

// ---------------- fused hop kernel --------------------------------------------
// One WARP per output row (entities first, then users). Each lane owns 8
// consecutive channels: gathers are one 16B (8 x fp16) load per lane per edge.
// Accumulation / norm / residual all fp32. BYTE-IDENTICAL to the verified
// optimum — do not touch (R6-R10 all regressed by modifying it).
__global__ void __launch_bounds__(256) k_hop(
                      int srcSel, int dstSel, int useEta, int hop0,
                      const float4* __restrict__ ent_in,
                      const float4* __restrict__ user4,
                      const float4* __restrict__ rel4,
                      float4* __restrict__ outE,
                      float4* __restrict__ outU) {
    const __half* srcH = g_enth[srcSel];
    int gw   = (blockIdx.x * blockDim.x + threadIdx.x) >> 5;
    int lane = threadIdx.x & 31;
    if (gw >= NENT + NUSR) return;

    float acc[8];
    #pragma unroll
    for (int k = 0; k < 8; k++) acc[k] = 0.f;

    if (gw < NENT) {
        int row = gw;
        int beg = g_off_e[row], end = g_off_e[row + 1];
        for (int p = beg; p < end; ++p) {
            EdgeE ed = g_pe[p];
            float rho = useEta ? ed.eta : ed.alpha;
            uint4 hv = ((const uint4*)(srcH + (long)ed.tail * DD))[lane];
            const __half2* hp = (const __half2*)&hv;
            const float4* rp = rel4 + (long)ed.rel * D4 + lane * 2;
            float4 r0 = rp[0], r1 = rp[1];
            float2 f0 = __half22float2(hp[0]);
            float2 f1 = __half22float2(hp[1]);
            float2 f2 = __half22float2(hp[2]);
            float2 f3 = __half22float2(hp[3]);
            acc[0] = fmaf(rho * r0.x, f0.x, acc[0]);
            acc[1] = fmaf(rho * r0.y, f0.y, acc[1]);
            acc[2] = fmaf(rho * r0.z, f1.x, acc[2]);
            acc[3] = fmaf(rho * r0.w, f1.y, acc[3]);
            acc[4] = fmaf(rho * r1.x, f2.x, acc[4]);
            acc[5] = fmaf(rho * r1.y, f2.y, acc[5]);
            acc[6] = fmaf(rho * r1.z, f3.x, acc[6]);
            acc[7] = fmaf(rho * r1.w, f3.y, acc[7]);
        }
        float inv = 1.0f / fmaxf((float)(end - beg), 1.0f);
        float ss = 0.f;
        #pragma unroll
        for (int k = 0; k < 8; k++) { acc[k] *= inv; ss = fmaf(acc[k], acc[k], ss); }
        #pragma unroll
        for (int o = 16; o > 0; o >>= 1) ss += __shfl_xor_sync(0xffffffffu, ss, o);
        float innorm = 1.0f / fmaxf(sqrtf(ss), EPSV);
        float v[8];
        #pragma unroll
        for (int k = 0; k < 8; k++) v[k] = cleanv(acc[k] * innorm);

        if (dstSel >= 0) {
            uint4 hv;
            __half2* hp = (__half2*)&hv;
            hp[0] = __floats2half2_rn(v[0], v[1]);
            hp[1] = __floats2half2_rn(v[2], v[3]);
            hp[2] = __floats2half2_rn(v[4], v[5]);
            hp[3] = __floats2half2_rn(v[6], v[7]);
            ((uint4*)(g_enth[dstSel] + (long)row * DD))[lane] = hv;
        }
        long o0 = (long)row * D4 + lane * 2;
        float4 b0 = hop0 ? ent_in[o0]     : outE[o0];
        float4 b1 = hop0 ? ent_in[o0 + 1] : outE[o0 + 1];
        outE[o0]     = make_float4(b0.x + v[0], b0.y + v[1], b0.z + v[2], b0.w + v[3]);
        outE[o0 + 1] = make_float4(b1.x + v[4], b1.y + v[5], b1.z + v[6], b1.w + v[7]);
    } else {
        int row = gw - NENT;
        int beg = g_off_u[row], end = g_off_u[row + 1];
        for (int p = beg; p < end; ++p) {
            EdgeU eu = g_pu[p];
            float w = eu.w;
            uint4 hv = ((const uint4*)(srcH + (long)eu.item * DD))[lane];
            const __half2* hp = (const __half2*)&hv;
            float2 f0 = __half22float2(hp[0]);
            float2 f1 = __half22float2(hp[1]);
            float2 f2 = __half22float2(hp[2]);
            float2 f3 = __half22float2(hp[3]);
            acc[0] = fmaf(w, f0.x, acc[0]);
            acc[1] = fmaf(w, f0.y, acc[1]);
            acc[2] = fmaf(w, f1.x, acc[2]);
            acc[3] = fmaf(w, f1.y, acc[3]);
            acc[4] = fmaf(w, f2.x, acc[4]);
            acc[5] = fmaf(w, f2.y, acc[5]);
            acc[6] = fmaf(w, f3.x, acc[6]);
            acc[7] = fmaf(w, f3.y, acc[7]);
        }
        float ss = 0.f;
        #pragma unroll
        for (int k = 0; k < 8; k++) ss = fmaf(acc[k], acc[k], ss);
        #pragma unroll
        for (int o = 16; o > 0; o >>= 1) ss += __shfl_xor_sync(0xffffffffu, ss, o);
        float innorm = 1.0f / fmaxf(sqrtf(ss), EPSV);
        float v[8];
        #pragma unroll
        for (int k = 0; k < 8; k++) v[k] = cleanv(acc[k] * innorm);

        long o0 = (long)row * D4 + lane * 2;
        float4 b0 = hop0 ? user4[o0]     : outU[o0];
        float4 b1 = hop0 ? user4[o0 + 1] : outU[o0 + 1];
        outU[o0]     = make_float4(b0.x + v[0], b0.y + v[1], b0.z + v[2], b0.w + v[3]);
        outU[o0 + 1] = make_float4(b1.x + v[4], b1.y + v[5], b1.z + v[6], b1.w + v[7]);
    }
}

// ---------------- launch ------------------------------------------------------
extern "C" void kernel_launch(void* const* d_in, const int* in_sizes, int n_in,
                              void* d_out, int out_size) {
    const float* user_emb   = (const float*)d_in[0];
    const float* entity_emb = (const float*)d_in[1];
    const int*   edge_index = (const int*)d_in[2];   // [2, E]
    const int*   edge_type  = (const int*)d_in[3];
    const float* omega      = (const float*)d_in[4];
    const int*   inter_edge = (const int*)d_in[5];   // [2, IE]
    const float* inter_w    = (const float*)d_in[6];
    const float* rel_emb    = (const float*)d_in[7];
    float* out = (float*)d_out;

    const int* head = edge_index;
    const int* tail = edge_index + ECNT;
    const int* iu   = inter_edge;
    const int* ii   = inter_edge + IECNT;

    const float4* ent_in = (const float4*)entity_emb;
    const float4* usr_in = (const float4*)user_emb;
    const float4* rel4   = (const float4*)rel_emb;
    float4* outE = (float4*)out;
    float4* outU = (float4*)(out + (long)NENT * DD);

    const int T = 256;
    const int EG = (ECNT + T - 1) / T;
    // invariant: cnt_e/cnt_u/seg_omega zero at entry (module load, or
    // k_fillconv from previous replay); seg_eta zeroed by k_count below.
    k_count   <<<EG, T>>>(head, omega, iu);                           // 0
    k_alpha   <<<EG, T>>>(head, omega);                               // 1
    k_scanA   <<<EB + UB, T>>>();                                     // 2
    k_scanBC  <<<EB + UB, T>>>();                                     // 3
    k_fillconv<<<EG, T>>>(head, tail, edge_type, iu, ii, inter_w,
                          (const float2*)entity_emb);                 // 4

    const int G = ((NENT + NUSR) * 32 + T - 1) / T;   // one warp per row
    // hop 1: src=fp16 input copy (2), dst=0 ; hop 2: 0->1 ; hop 3: 1-> (no state write)
    k_hop<<<G, T>>>(2,  0, /*useEta=*/0, /*hop0=*/1, ent_in, usr_in, rel4, outE, outU);  // 5 (profiled)
    k_hop<<<G, T>>>(0,  1, /*useEta=*/0, /*hop0=*/0, ent_in, usr_in, rel4, outE, outU);
    k_hop<<<G, T>>>(1, -1, /*useEta=*/1, /*hop0=*/0, ent_in, usr_in, rel4, outE, outU);
}

// round 15
// speedup vs baseline: 1.2819x; 1.2819x over previous
#include <cuda_runtime.h>
#include <cuda_fp16.h>
#include <math.h>

#define ECNT   300000
#define IECNT  300000
#define NENT   100000
#define NUSR   50000
#define DD     256
#define D4     64
#define EPSV   1e-8f
#define GAMMAV 0.2f

#define TILE   4096
#define EB     ((NENT + TILE - 1) / TILE)   // 25
#define UB     ((NUSR + TILE - 1) / TILE)   // 13

struct EdgeE { int tail; int rel; float alpha; float eta; };   // 16B
struct EdgeU { int item; float w; };                           // 8B

// ---------------- scratch (device globals; no allocations allowed) -----------
// Zero-invariant (cnt_e, cnt_u, seg_omega zero at k_count entry; seg_eta zero
// at k_alpha entry) is established by module load on call 1 and re-established
// every replay: k_count zeroes seg_eta, k_fillconv zeroes cnt/seg_omega.
__device__ int    g_cnt_e[NENT];
__device__ int    g_cnt_u[NUSR];
__device__ float  g_seg_omega[NENT];
__device__ float  g_seg_eta[NENT];
__device__ int    g_off_e[NENT + 1];
__device__ int    g_off_u[NUSR + 1];
__device__ int    g_cur_e[NENT];
__device__ int    g_cur_u[NUSR];
__device__ int    g_tilesum[EB + UB];
__device__ float  g_alpha[ECNT];
__device__ float  g_eta0[ECNT];
__device__ EdgeE  g_pe[ECNT];
__device__ EdgeU  g_pu[IECNT];
// fp16 entity states: [0],[1] = ping-pong hop states, [2] = fp16 copy of input
__device__ __half g_enth[3][NENT * DD];

// ---------------- helpers ----------------------------------------------------
__device__ __forceinline__ float cleanv(float v) {
    if (isnan(v)) return 0.0f;
    if (isinf(v)) return v > 0.f ? 10000.0f : 0.0001f;
    return v;
}

// ---------------- precompute --------------------------------------------------
// Also zeroes g_seg_eta (accumulated by the NEXT kernel, k_alpha) so no
// separate cleanup launch is needed.
__global__ void k_count(const int* __restrict__ head, const float* __restrict__ omega,
                        const int* __restrict__ iu) {
    int e = blockIdx.x * blockDim.x + threadIdx.x;
    if (e < NENT) g_seg_eta[e] = 0.f;
    if (e < ECNT) {
        int h = head[e];
        atomicAdd(&g_cnt_e[h], 1);
        atomicAdd(&g_seg_omega[h], omega[e]);
    }
    if (e < IECNT) {
        atomicAdd(&g_cnt_u[iu[e]], 1);
    }
}

__global__ void k_alpha(const int* __restrict__ head, const float* __restrict__ omega) {
    int e = blockIdx.x * blockDim.x + threadIdx.x;
    if (e < ECNT) {
        int h = head[e];
        float a = omega[e] / (g_seg_omega[h] + EPSV);
        g_alpha[e] = a;
        float e0 = (a > GAMMAV) ? a : 0.0f;
        g_eta0[e] = e0;
        atomicAdd(&g_seg_eta[h], e0);
    }
}

// Pass A: per-tile sums (38 independent blocks). Order-free, so reads are
// interleaved for perfect coalescing (cnt[tile + k*256 + t]).
__global__ void k_scanA() {
    int b = blockIdx.x;
    int which = (b >= EB);
    int tb = which ? b - EB : b;
    const int* cnt = which ? g_cnt_u : g_cnt_e;
    int n          = which ? NUSR    : NENT;
    int tbase = tb * TILE;
    int s = 0;
    #pragma unroll
    for (int k = 0; k < 16; k++) {
        int i = tbase + k * 256 + threadIdx.x;
        s += (i < n) ? cnt[i] : 0;
    }
    __shared__ int sh[8];
    int lane = threadIdx.x & 31, wid = threadIdx.x >> 5;
    #pragma unroll
    for (int o = 16; o > 0; o >>= 1) s += __shfl_down_sync(0xffffffffu, s, o);
    if (lane == 0) sh[wid] = s;
    __syncthreads();
    if (threadIdx.x == 0) {
        int t = 0;
        #pragma unroll
        for (int i = 0; i < 8; i++) t += sh[i];
        g_tilesum[b] = t;
    }
}

// Pass B+C merged: each block redundantly scans the tile sums of its segment,
// then re-scans its own tile with the global offset.
__global__ void k_scanBC() {
    int b = blockIdx.x;
    int which = (b >= EB);
    int tb = which ? b - EB : b;
    const int* cnt = which ? g_cnt_u : g_cnt_e;
    int* off       = which ? g_off_u : g_off_e;
    int* cur       = which ? g_cur_u : g_cur_e;
    int n          = which ? NUSR    : NENT;
    int nb         = which ? UB      : EB;
    int sbase      = which ? EB      : 0;

    __shared__ int s_tileoff;
    if (threadIdx.x < 32) {
        int lane = threadIdx.x;
        int v = (lane < nb) ? g_tilesum[sbase + lane] : 0;
        int x = v;
        #pragma unroll
        for (int o = 1; o < 32; o <<= 1) {
            int y = __shfl_up_sync(0xffffffffu, x, o);
            if (lane >= o) x += y;
        }
        if (lane == tb) s_tileoff = x - v;
    }
    __syncthreads();

    int t = threadIdx.x;
    int lane = t & 31, wid = t >> 5;
    int base = tb * TILE + t * 16;
    int v[16], loc = 0;
    #pragma unroll
    for (int k = 0; k < 16; k++) {
        int i = base + k;
        v[k] = (i < n) ? cnt[i] : 0;
        loc += v[k];
    }
    int x = loc;
    #pragma unroll
    for (int o = 1; o < 32; o <<= 1) {
        int y = __shfl_up_sync(0xffffffffu, x, o);
        if (lane >= o) x += y;
    }
    __shared__ int warpsum[8];
    if (lane == 31) warpsum[wid] = x;
    __syncthreads();
    int wpre = 0;
    #pragma unroll
    for (int i = 0; i < 8; i++) wpre += (i < wid) ? warpsum[i] : 0;
    int excl = s_tileoff + wpre + (x - loc);
    #pragma unroll
    for (int k = 0; k < 16; k++) {
        int i = base + k;
        if (i < n) { off[i] = excl; cur[i] = excl; }
        else if (i == n) { off[n] = excl; }
        excl += v[k];
    }
}

// CSR fill (packed payloads) + fp16 conversion of the input entity embedding.
// Also restores the zero-invariant for cnt_e / cnt_u / seg_omega (their last
// readers, k_scanBC / k_alpha, have already completed).
__global__ void k_fillconv(const int* __restrict__ head, const int* __restrict__ tail,
                           const int* __restrict__ etype,
                           const int* __restrict__ iu, const int* __restrict__ ii,
                           const float* __restrict__ w,
                           const float2* __restrict__ ent_in2) {
    int e = blockIdx.x * blockDim.x + threadIdx.x;
    if (e < ECNT) {
        int h = head[e];
        int pos = atomicAdd(&g_cur_e[h], 1);
        EdgeE ed;
        ed.tail  = tail[e];
        ed.rel   = etype[e] - 1;
        ed.alpha = g_alpha[e];
        ed.eta   = g_eta0[e] / (g_seg_eta[h] + EPSV);
        g_pe[pos] = ed;
    }
    if (e < IECNT) {
        int u = iu[e];
        int pos = atomicAdd(&g_cur_u[u], 1);
        EdgeU eu;
        eu.item = ii[e];
        eu.w    = w[e];
        g_pu[pos] = eu;
    }
    // restore zero-invariant for next replay
    if (e < NENT) { g_cnt_e[e] = 0; g_seg_omega[e] = 0.f; }
    if (e < NUSR) { g_cnt_u[e] = 0; }
    // fp16 copy of the input entity embedding (grid-stride)
    __half2* dst = (__half2*)g_enth[2];
    long total = (long)gridDim.x * blockDim.x;
    const long NH2 = (long)NENT * DD / 2;
    for (long i = e; i < NH2; i += total) {
        dst[i] = __float22half2_rn(ent_in2[i]);
    }
}

// ---------------- fused hop kernel --------------------------------------------
// One WARP per output row (entities first, then users). Each lane owns 8
// consecutive channels: gathers are one 16B (8 x fp16) load per lane per edge.
// Accumulation / norm / residual all fp32. BYTE-IDENTICAL to the verified
// optimum — do not touch.
__global__ void __launch_bounds__(256) k_hop(
                      int srcSel, int dstSel, int useEta, int hop0,
                      const float4* __restrict__ ent_in,
                      const float4* __restrict__ user4,
                      const float4* __restrict__ rel4,
                      float4* __restrict__ outE,
                      float4* __restrict__ outU) {
    const __half* srcH = g_enth[srcSel];
    int gw   = (blockIdx.x * blockDim.x + threadIdx.x) >> 5;
    int lane = threadIdx.x & 31;
    if (gw >= NENT + NUSR) return;

    float acc[8];
    #pragma unroll
    for (int k = 0; k < 8; k++) acc[k] = 0.f;

    if (gw < NENT) {
        int row = gw;
        int beg = g_off_e[row], end = g_off_e[row + 1];
        for (int p = beg; p < end; ++p) {
            EdgeE ed = g_pe[p];
            float rho = useEta ? ed.eta : ed.alpha;
            uint4 hv = ((const uint4*)(srcH + (long)ed.tail * DD))[lane];
            const __half2* hp = (const __half2*)&hv;
            const float4* rp = rel4 + (long)ed.rel * D4 + lane * 2;
            float4 r0 = rp[0], r1 = rp[1];
            float2 f0 = __half22float2(hp[0]);
            float2 f1 = __half22float2(hp[1]);
            float2 f2 = __half22float2(hp[2]);
            float2 f3 = __half22float2(hp[3]);
            acc[0] = fmaf(rho * r0.x, f0.x, acc[0]);
            acc[1] = fmaf(rho * r0.y, f0.y, acc[1]);
            acc[2] = fmaf(rho * r0.z, f1.x, acc[2]);
            acc[3] = fmaf(rho * r0.w, f1.y, acc[3]);
            acc[4] = fmaf(rho * r1.x, f2.x, acc[4]);
            acc[5] = fmaf(rho * r1.y, f2.y, acc[5]);
            acc[6] = fmaf(rho * r1.z, f3.x, acc[6]);
            acc[7] = fmaf(rho * r1.w, f3.y, acc[7]);
        }
        float inv = 1.0f / fmaxf((float)(end - beg), 1.0f);
        float ss = 0.f;
        #pragma unroll
        for (int k = 0; k < 8; k++) { acc[k] *= inv; ss = fmaf(acc[k], acc[k], ss); }
        #pragma unroll
        for (int o = 16; o > 0; o >>= 1) ss += __shfl_xor_sync(0xffffffffu, ss, o);
        float innorm = 1.0f / fmaxf(sqrtf(ss), EPSV);
        float v[8];
        #pragma unroll
        for (int k = 0; k < 8; k++) v[k] = cleanv(acc[k] * innorm);

        if (dstSel >= 0) {
            uint4 hv;
            __half2* hp = (__half2*)&hv;
            hp[0] = __floats2half2_rn(v[0], v[1]);
            hp[1] = __floats2half2_rn(v[2], v[3]);
            hp[2] = __floats2half2_rn(v[4], v[5]);
            hp[3] = __floats2half2_rn(v[6], v[7]);
            ((uint4*)(g_enth[dstSel] + (long)row * DD))[lane] = hv;
        }
        long o0 = (long)row * D4 + lane * 2;
        float4 b0 = hop0 ? ent_in[o0]     : outE[o0];
        float4 b1 = hop0 ? ent_in[o0 + 1] : outE[o0 + 1];
        outE[o0]     = make_float4(b0.x + v[0], b0.y + v[1], b0.z + v[2], b0.w + v[3]);
        outE[o0 + 1] = make_float4(b1.x + v[4], b1.y + v[5], b1.z + v[6], b1.w + v[7]);
    } else {
        int row = gw - NENT;
        int beg = g_off_u[row], end = g_off_u[row + 1];
        for (int p = beg; p < end; ++p) {
            EdgeU eu = g_pu[p];
            float w = eu.w;
            uint4 hv = ((const uint4*)(srcH + (long)eu.item * DD))[lane];
            const __half2* hp = (const __half2*)&hv;
            float2 f0 = __half22float2(hp[0]);
            float2 f1 = __half22float2(hp[1]);
            float2 f2 = __half22float2(hp[2]);
            float2 f3 = __half22float2(hp[3]);
            acc[0] = fmaf(w, f0.x, acc[0]);
            acc[1] = fmaf(w, f0.y, acc[1]);
            acc[2] = fmaf(w, f1.x, acc[2]);
            acc[3] = fmaf(w, f1.y, acc[3]);
            acc[4] = fmaf(w, f2.x, acc[4]);
            acc[5] = fmaf(w, f2.y, acc[5]);
            acc[6] = fmaf(w, f3.x, acc[6]);
            acc[7] = fmaf(w, f3.y, acc[7]);
        }
        float ss = 0.f;
        #pragma unroll
        for (int k = 0; k < 8; k++) ss = fmaf(acc[k], acc[k], ss);
        #pragma unroll
        for (int o = 16; o > 0; o >>= 1) ss += __shfl_xor_sync(0xffffffffu, ss, o);
        float innorm = 1.0f / fmaxf(sqrtf(ss), EPSV);
        float v[8];
        #pragma unroll
        for (int k = 0; k < 8; k++) v[k] = cleanv(acc[k] * innorm);

        long o0 = (long)row * D4 + lane * 2;
        float4 b0 = hop0 ? user4[o0]     : outU[o0];
        float4 b1 = hop0 ? user4[o0 + 1] : outU[o0 + 1];
        outU[o0]     = make_float4(b0.x + v[0], b0.y + v[1], b0.z + v[2], b0.w + v[3]);
        outU[o0 + 1] = make_float4(b1.x + v[4], b1.y + v[5], b1.z + v[6], b1.w + v[7]);
    }
}

// ---------------- launch ------------------------------------------------------
extern "C" void kernel_launch(void* const* d_in, const int* in_sizes, int n_in,
                              void* d_out, int out_size) {
    const float* user_emb   = (const float*)d_in[0];
    const float* entity_emb = (const float*)d_in[1];
    const int*   edge_index = (const int*)d_in[2];   // [2, E]
    const int*   edge_type  = (const int*)d_in[3];
    const float* omega      = (const float*)d_in[4];
    const int*   inter_edge = (const int*)d_in[5];   // [2, IE]
    const float* inter_w    = (const float*)d_in[6];
    const float* rel_emb    = (const float*)d_in[7];
    float* out = (float*)d_out;

    const int* head = edge_index;
    const int* tail = edge_index + ECNT;
    const int* iu   = inter_edge;
    const int* ii   = inter_edge + IECNT;

    const float4* ent_in = (const float4*)entity_emb;
    const float4* usr_in = (const float4*)user_emb;
    const float4* rel4   = (const float4*)rel_emb;
    float4* outE = (float4*)out;
    float4* outU = (float4*)(out + (long)NENT * DD);

    const int T = 256;
    const int EG = (ECNT + T - 1) / T;
    // invariant: cnt_e/cnt_u/seg_omega zero at entry (module load, or
    // k_fillconv from previous replay); seg_eta zeroed by k_count below.
    k_count   <<<EG, T>>>(head, omega, iu);                           // 0
    k_alpha   <<<EG, T>>>(head, omega);                               // 1
    k_scanA   <<<EB + UB, T>>>();                                     // 2
    k_scanBC  <<<EB + UB, T>>>();                                     // 3
    k_fillconv<<<EG, T>>>(head, tail, edge_type, iu, ii, inter_w,
                          (const float2*)entity_emb);                 // 4

    const int G = ((NENT + NUSR) * 32 + T - 1) / T;   // one warp per row
    // hop 1: src=fp16 input copy (2), dst=0 ; hop 2: 0->1 ; hop 3: 1-> (no state write)
    k_hop<<<G, T>>>(2,  0, /*useEta=*/0, /*hop0=*/1, ent_in, usr_in, rel4, outE, outU);  // 5 (profiled)
    k_hop<<<G, T>>>(0,  1, /*useEta=*/0, /*hop0=*/0, ent_in, usr_in, rel4, outE, outU);
    k_hop<<<G, T>>>(1, -1, /*useEta=*/1, /*hop0=*/0, ent_in, usr_in, rel4, outE, outU);
}

// round 16
// speedup vs baseline: 1.3095x; 1.0215x over previous
#include <cuda_runtime.h>
#include <cuda_fp16.h>
#include <math.h>

#define ECNT   300000
#define IECNT  300000
#define NENT   100000
#define NUSR   50000
#define DD     256
#define D4     64
#define EPSV   1e-8f
#define GAMMAV 0.2f

#define TILE   4096
#define EB     ((NENT + TILE - 1) / TILE)   // 25
#define UB     ((NUSR + TILE - 1) / TILE)   // 13

struct EdgeE { int tail; int rel; float alpha; float eta; };   // 16B
struct EdgeU { int item; float w; };                           // 8B

// ---------------- scratch (device globals; no allocations allowed) -----------
// Zero-invariant (cnt_e, cnt_u, seg_omega zero at k_count entry; seg_eta zero
// at k_alpha entry) is established by module load on call 1 and re-established
// every replay: k_count zeroes seg_eta, k_fillconv zeroes cnt/seg_omega.
__device__ int    g_cnt_e[NENT];
__device__ int    g_cnt_u[NUSR];
__device__ float  g_seg_omega[NENT];
__device__ float  g_seg_eta[NENT];
__device__ int    g_off_e[NENT + 1];
__device__ int    g_off_u[NUSR + 1];
__device__ int    g_cur_e[NENT];
__device__ int    g_cur_u[NUSR];
__device__ int    g_tilesum[EB + UB];
__device__ float  g_alpha[ECNT];
__device__ float  g_eta0[ECNT];
__device__ EdgeE  g_pe[ECNT];
__device__ EdgeU  g_pu[IECNT];
// fp16 entity states: [0]=v1, [1]=v2, [2]=fp16 copy of input embedding
__device__ __half g_enth[3][NENT * DD];
// fp16 user states: [0]=u1, [1]=u2
__device__ __half g_usrh[2][NUSR * DD];

// ---------------- helpers ----------------------------------------------------
__device__ __forceinline__ float cleanv(float v) {
    if (isnan(v)) return 0.0f;
    if (isinf(v)) return v > 0.f ? 10000.0f : 0.0001f;
    return v;
}

// ---------------- precompute --------------------------------------------------
__global__ void k_count(const int* __restrict__ head, const float* __restrict__ omega,
                        const int* __restrict__ iu) {
    int e = blockIdx.x * blockDim.x + threadIdx.x;
    if (e < NENT) g_seg_eta[e] = 0.f;
    if (e < ECNT) {
        int h = head[e];
        atomicAdd(&g_cnt_e[h], 1);
        atomicAdd(&g_seg_omega[h], omega[e]);
    }
    if (e < IECNT) {
        atomicAdd(&g_cnt_u[iu[e]], 1);
    }
}

__global__ void k_alpha(const int* __restrict__ head, const float* __restrict__ omega) {
    int e = blockIdx.x * blockDim.x + threadIdx.x;
    if (e < ECNT) {
        int h = head[e];
        float a = omega[e] / (g_seg_omega[h] + EPSV);
        g_alpha[e] = a;
        float e0 = (a > GAMMAV) ? a : 0.0f;
        g_eta0[e] = e0;
        atomicAdd(&g_seg_eta[h], e0);
    }
}

// Pass A: per-tile sums (38 independent blocks), coalesced interleaved reads.
__global__ void k_scanA() {
    int b = blockIdx.x;
    int which = (b >= EB);
    int tb = which ? b - EB : b;
    const int* cnt = which ? g_cnt_u : g_cnt_e;
    int n          = which ? NUSR    : NENT;
    int tbase = tb * TILE;
    int s = 0;
    #pragma unroll
    for (int k = 0; k < 16; k++) {
        int i = tbase + k * 256 + threadIdx.x;
        s += (i < n) ? cnt[i] : 0;
    }
    __shared__ int sh[8];
    int lane = threadIdx.x & 31, wid = threadIdx.x >> 5;
    #pragma unroll
    for (int o = 16; o > 0; o >>= 1) s += __shfl_down_sync(0xffffffffu, s, o);
    if (lane == 0) sh[wid] = s;
    __syncthreads();
    if (threadIdx.x == 0) {
        int t = 0;
        #pragma unroll
        for (int i = 0; i < 8; i++) t += sh[i];
        g_tilesum[b] = t;
    }
}

// Pass B+C merged.
__global__ void k_scanBC() {
    int b = blockIdx.x;
    int which = (b >= EB);
    int tb = which ? b - EB : b;
    const int* cnt = which ? g_cnt_u : g_cnt_e;
    int* off       = which ? g_off_u : g_off_e;
    int* cur       = which ? g_cur_u : g_cur_e;
    int n          = which ? NUSR    : NENT;
    int nb         = which ? UB      : EB;
    int sbase      = which ? EB      : 0;

    __shared__ int s_tileoff;
    if (threadIdx.x < 32) {
        int lane = threadIdx.x;
        int v = (lane < nb) ? g_tilesum[sbase + lane] : 0;
        int x = v;
        #pragma unroll
        for (int o = 1; o < 32; o <<= 1) {
            int y = __shfl_up_sync(0xffffffffu, x, o);
            if (lane >= o) x += y;
        }
        if (lane == tb) s_tileoff = x - v;
    }
    __syncthreads();

    int t = threadIdx.x;
    int lane = t & 31, wid = t >> 5;
    int base = tb * TILE + t * 16;
    int v[16], loc = 0;
    #pragma unroll
    for (int k = 0; k < 16; k++) {
        int i = base + k;
        v[k] = (i < n) ? cnt[i] : 0;
        loc += v[k];
    }
    int x = loc;
    #pragma unroll
    for (int o = 1; o < 32; o <<= 1) {
        int y = __shfl_up_sync(0xffffffffu, x, o);
        if (lane >= o) x += y;
    }
    __shared__ int warpsum[8];
    if (lane == 31) warpsum[wid] = x;
    __syncthreads();
    int wpre = 0;
    #pragma unroll
    for (int i = 0; i < 8; i++) wpre += (i < wid) ? warpsum[i] : 0;
    int excl = s_tileoff + wpre + (x - loc);
    #pragma unroll
    for (int k = 0; k < 16; k++) {
        int i = base + k;
        if (i < n) { off[i] = excl; cur[i] = excl; }
        else if (i == n) { off[n] = excl; }
        excl += v[k];
    }
}

// CSR fill + fp16 conversion of the input entity embedding + zero-invariant
// restoration (no separate cleanup launch).
__global__ void k_fillconv(const int* __restrict__ head, const int* __restrict__ tail,
                           const int* __restrict__ etype,
                           const int* __restrict__ iu, const int* __restrict__ ii,
                           const float* __restrict__ w,
                           const float2* __restrict__ ent_in2) {
    int e = blockIdx.x * blockDim.x + threadIdx.x;
    if (e < ECNT) {
        int h = head[e];
        int pos = atomicAdd(&g_cur_e[h], 1);
        EdgeE ed;
        ed.tail  = tail[e];
        ed.rel   = etype[e] - 1;
        ed.alpha = g_alpha[e];
        ed.eta   = g_eta0[e] / (g_seg_eta[h] + EPSV);
        g_pe[pos] = ed;
    }
    if (e < IECNT) {
        int u = iu[e];
        int pos = atomicAdd(&g_cur_u[u], 1);
        EdgeU eu;
        eu.item = ii[e];
        eu.w    = w[e];
        g_pu[pos] = eu;
    }
    if (e < NENT) { g_cnt_e[e] = 0; g_seg_omega[e] = 0.f; }
    if (e < NUSR) { g_cnt_u[e] = 0; }
    __half2* dst = (__half2*)g_enth[2];
    long total = (long)gridDim.x * blockDim.x;
    const long NH2 = (long)NENT * DD / 2;
    for (long i = e; i < NH2; i += total) {
        dst[i] = __float22half2_rn(ent_in2[i]);
    }
}

// ---------------- fused hop kernel (deferred residual) ------------------------
// One WARP per output row, lane owns 8 channels, identical gather/norm shape
// to the 371us champion. hopIdx 0/1: write fp16 state only (NO out traffic).
// hopIdx 2: fused epilogue — out = input + v1 + v2 + v3 in a single pass.
__global__ void __launch_bounds__(256) k_hop(
                      int hopIdx,
                      const float4* __restrict__ ent_in,
                      const float4* __restrict__ user4,
                      const float4* __restrict__ rel4,
                      float4* __restrict__ outE,
                      float4* __restrict__ outU) {
    const int srcSel = (hopIdx == 0) ? 2 : (hopIdx - 1);
    const __half* srcH = g_enth[srcSel];
    int gw   = (blockIdx.x * blockDim.x + threadIdx.x) >> 5;
    int lane = threadIdx.x & 31;
    if (gw >= NENT + NUSR) return;

    float acc[8];
    #pragma unroll
    for (int k = 0; k < 8; k++) acc[k] = 0.f;

    if (gw < NENT) {
        int row = gw;
        int beg = g_off_e[row], end = g_off_e[row + 1];
        const bool useEta = (hopIdx == 2);
        for (int p = beg; p < end; ++p) {
            EdgeE ed = g_pe[p];
            float rho = useEta ? ed.eta : ed.alpha;
            uint4 hv = ((const uint4*)(srcH + (long)ed.tail * DD))[lane];
            const __half2* hp = (const __half2*)&hv;
            const float4* rp = rel4 + (long)ed.rel * D4 + lane * 2;
            float4 r0 = rp[0], r1 = rp[1];
            float2 f0 = __half22float2(hp[0]);
            float2 f1 = __half22float2(hp[1]);
            float2 f2 = __half22float2(hp[2]);
            float2 f3 = __half22float2(hp[3]);
            acc[0] = fmaf(rho * r0.x, f0.x, acc[0]);
            acc[1] = fmaf(rho * r0.y, f0.y, acc[1]);
            acc[2] = fmaf(rho * r0.z, f1.x, acc[2]);
            acc[3] = fmaf(rho * r0.w, f1.y, acc[3]);
            acc[4] = fmaf(rho * r1.x, f2.x, acc[4]);
            acc[5] = fmaf(rho * r1.y, f2.y, acc[5]);
            acc[6] = fmaf(rho * r1.z, f3.x, acc[6]);
            acc[7] = fmaf(rho * r1.w, f3.y, acc[7]);
        }
        float inv = 1.0f / fmaxf((float)(end - beg), 1.0f);
        float ss = 0.f;
        #pragma unroll
        for (int k = 0; k < 8; k++) { acc[k] *= inv; ss = fmaf(acc[k], acc[k], ss); }
        #pragma unroll
        for (int o = 16; o > 0; o >>= 1) ss += __shfl_xor_sync(0xffffffffu, ss, o);
        float innorm = 1.0f / fmaxf(sqrtf(ss), EPSV);
        float v[8];
        #pragma unroll
        for (int k = 0; k < 8; k++) v[k] = cleanv(acc[k] * innorm);

        if (hopIdx < 2) {
            uint4 hv;
            __half2* hp = (__half2*)&hv;
            hp[0] = __floats2half2_rn(v[0], v[1]);
            hp[1] = __floats2half2_rn(v[2], v[3]);
            hp[2] = __floats2half2_rn(v[4], v[5]);
            hp[3] = __floats2half2_rn(v[6], v[7]);
            ((uint4*)(g_enth[hopIdx] + (long)row * DD))[lane] = hv;
        } else {
            uint4 h1 = ((const uint4*)(g_enth[0] + (long)row * DD))[lane];
            uint4 h2 = ((const uint4*)(g_enth[1] + (long)row * DD))[lane];
            const __half2* p1 = (const __half2*)&h1;
            const __half2* p2 = (const __half2*)&h2;
            float s[8];
            #pragma unroll
            for (int q = 0; q < 4; q++) {
                float2 a = __half22float2(p1[q]);
                float2 b = __half22float2(p2[q]);
                s[q * 2]     = a.x + b.x;
                s[q * 2 + 1] = a.y + b.y;
            }
            long o0 = (long)row * D4 + lane * 2;
            float4 b0 = ent_in[o0];
            float4 b1 = ent_in[o0 + 1];
            outE[o0]     = make_float4(b0.x + s[0] + v[0], b0.y + s[1] + v[1],
                                       b0.z + s[2] + v[2], b0.w + s[3] + v[3]);
            outE[o0 + 1] = make_float4(b1.x + s[4] + v[4], b1.y + s[5] + v[5],
                                       b1.z + s[6] + v[6], b1.w + s[7] + v[7]);
        }
    } else {
        int row = gw - NENT;
        int beg = g_off_u[row], end = g_off_u[row + 1];
        for (int p = beg; p < end; ++p) {
            EdgeU eu = g_pu[p];
            float w = eu.w;
            uint4 hv = ((const uint4*)(srcH + (long)eu.item * DD))[lane];
            const __half2* hp = (const __half2*)&hv;
            float2 f0 = __half22float2(hp[0]);
            float2 f1 = __half22float2(hp[1]);
            float2 f2 = __half22float2(hp[2]);
            float2 f3 = __half22float2(hp[3]);
            acc[0] = fmaf(w, f0.x, acc[0]);
            acc[1] = fmaf(w, f0.y, acc[1]);
            acc[2] = fmaf(w, f1.x, acc[2]);
            acc[3] = fmaf(w, f1.y, acc[3]);
            acc[4] = fmaf(w, f2.x, acc[4]);
            acc[5] = fmaf(w, f2.y, acc[5]);
            acc[6] = fmaf(w, f3.x, acc[6]);
            acc[7] = fmaf(w, f3.y, acc[7]);
        }
        float ss = 0.f;
        #pragma unroll
        for (int k = 0; k < 8; k++) ss = fmaf(acc[k], acc[k], ss);
        #pragma unroll
        for (int o = 16; o > 0; o >>= 1) ss += __shfl_xor_sync(0xffffffffu, ss, o);
        float innorm = 1.0f / fmaxf(sqrtf(ss), EPSV);
        float v[8];
        #pragma unroll
        for (int k = 0; k < 8; k++) v[k] = cleanv(acc[k] * innorm);

        if (hopIdx < 2) {
            uint4 hv;
            __half2* hp = (__half2*)&hv;
            hp[0] = __floats2half2_rn(v[0], v[1]);
            hp[1] = __floats2half2_rn(v[2], v[3]);
            hp[2] = __floats2half2_rn(v[4], v[5]);
            hp[3] = __floats2half2_rn(v[6], v[7]);
            ((uint4*)(g_usrh[hopIdx] + (long)row * DD))[lane] = hv;
        } else {
            uint4 h1 = ((const uint4*)(g_usrh[0] + (long)row * DD))[lane];
            uint4 h2 = ((const uint4*)(g_usrh[1] + (long)row * DD))[lane];
            const __half2* p1 = (const __half2*)&h1;
            const __half2* p2 = (const __half2*)&h2;
            float s[8];
            #pragma unroll
            for (int q = 0; q < 4; q++) {
                float2 a = __half22float2(p1[q]);
                float2 b = __half22float2(p2[q]);
                s[q * 2]     = a.x + b.x;
                s[q * 2 + 1] = a.y + b.y;
            }
            long o0 = (long)row * D4 + lane * 2;
            float4 b0 = user4[o0];
            float4 b1 = user4[o0 + 1];
            outU[o0]     = make_float4(b0.x + s[0] + v[0], b0.y + s[1] + v[1],
                                       b0.z + s[2] + v[2], b0.w + s[3] + v[3]);
            outU[o0 + 1] = make_float4(b1.x + s[4] + v[4], b1.y + s[5] + v[5],
                                       b1.z + s[6] + v[6], b1.w + s[7] + v[7]);
        }
    }
}

// ---------------- launch ------------------------------------------------------
extern "C" void kernel_launch(void* const* d_in, const int* in_sizes, int n_in,
                              void* d_out, int out_size) {
    const float* user_emb   = (const float*)d_in[0];
    const float* entity_emb = (const float*)d_in[1];
    const int*   edge_index = (const int*)d_in[2];   // [2, E]
    const int*   edge_type  = (const int*)d_in[3];
    const float* omega      = (const float*)d_in[4];
    const int*   inter_edge = (const int*)d_in[5];   // [2, IE]
    const float* inter_w    = (const float*)d_in[6];
    const float* rel_emb    = (const float*)d_in[7];
    float* out = (float*)d_out;

    const int* head = edge_index;
    const int* tail = edge_index + ECNT;
    const int* iu   = inter_edge;
    const int* ii   = inter_edge + IECNT;

    const float4* ent_in = (const float4*)entity_emb;
    const float4* usr_in = (const float4*)user_emb;
    const float4* rel4   = (const float4*)rel_emb;
    float4* outE = (float4*)out;
    float4* outU = (float4*)(out + (long)NENT * DD);

    const int T = 256;
    const int EG = (ECNT + T - 1) / T;
    k_count   <<<EG, T>>>(head, omega, iu);                           // 0
    k_alpha   <<<EG, T>>>(head, omega);                               // 1
    k_scanA   <<<EB + UB, T>>>();                                     // 2
    k_scanBC  <<<EB + UB, T>>>();                                     // 3
    k_fillconv<<<EG, T>>>(head, tail, edge_type, iu, ii, inter_w,
                          (const float2*)entity_emb);                 // 4

    const int G = ((NENT + NUSR) * 32 + T - 1) / T;   // one warp per row
    k_hop<<<G, T>>>(0, ent_in, usr_in, rel4, outE, outU);             // 5 (profiled)
    k_hop<<<G, T>>>(1, ent_in, usr_in, rel4, outE, outU);
    k_hop<<<G, T>>>(2, ent_in, usr_in, rel4, outE, outU);
}

// round 17
// speedup vs baseline: 1.3270x; 1.0134x over previous
#include <cuda_runtime.h>
#include <cuda_fp16.h>
#include <math.h>

#define ECNT   300000
#define IECNT  300000
#define NENT   100000
#define NUSR   50000
#define DD     256
#define D4     64
#define EPSV   1e-8f
#define GAMMAV 0.2f

#define TILE   4096
#define EB     ((NENT + TILE - 1) / TILE)   // 25
#define UB     ((NUSR + TILE - 1) / TILE)   // 13

struct EdgeE { int tail; int rel; float alpha; float eta; };   // 16B
struct EdgeU { int item; float w; };                           // 8B

// ---------------- scratch (device globals; no allocations allowed) -----------
// Zero-invariant (cnt_e, cnt_u, seg_omega zero at k_count entry; seg_eta zero
// at k_alpha entry) is established by module load on call 1 and re-established
// every replay: k_count zeroes seg_eta, k_fillconv zeroes cnt/seg_omega.
__device__ int    g_cnt_e[NENT];
__device__ int    g_cnt_u[NUSR];
__device__ float  g_seg_omega[NENT];
__device__ float  g_seg_eta[NENT];
__device__ int    g_off_e[NENT + 1];
__device__ int    g_off_u[NUSR + 1];
__device__ int    g_cur_e[NENT];
__device__ int    g_cur_u[NUSR];
__device__ int    g_tilesum[EB + UB];
__device__ float  g_alpha[ECNT];
__device__ float  g_eta0[ECNT];
__device__ EdgeE  g_pe[ECNT];
__device__ EdgeU  g_pu[IECNT];
// fp16 entity states: [0]=v1, [1]=v2, [2]=fp16 copy of input embedding
__device__ __half g_enth[3][NENT * DD];
// fp16 user states: [0]=u1, [1]=u2
__device__ __half g_usrh[2][NUSR * DD];

// ---------------- helpers ----------------------------------------------------
__device__ __forceinline__ float cleanv(float v) {
    if (isnan(v)) return 0.0f;
    if (isinf(v)) return v > 0.f ? 10000.0f : 0.0001f;
    return v;
}

// ---------------- precompute --------------------------------------------------
__global__ void k_count(const int* __restrict__ head, const float* __restrict__ omega,
                        const int* __restrict__ iu) {
    int e = blockIdx.x * blockDim.x + threadIdx.x;
    if (e < NENT) g_seg_eta[e] = 0.f;
    if (e < ECNT) {
        int h = head[e];
        atomicAdd(&g_cnt_e[h], 1);
        atomicAdd(&g_seg_omega[h], omega[e]);
    }
    if (e < IECNT) {
        atomicAdd(&g_cnt_u[iu[e]], 1);
    }
}

__global__ void k_alpha(const int* __restrict__ head, const float* __restrict__ omega) {
    int e = blockIdx.x * blockDim.x + threadIdx.x;
    if (e < ECNT) {
        int h = head[e];
        float a = omega[e] / (g_seg_omega[h] + EPSV);
        g_alpha[e] = a;
        float e0 = (a > GAMMAV) ? a : 0.0f;
        g_eta0[e] = e0;
        atomicAdd(&g_seg_eta[h], e0);
    }
}

// Pass A: per-tile sums (38 independent blocks), coalesced interleaved reads.
__global__ void k_scanA() {
    int b = blockIdx.x;
    int which = (b >= EB);
    int tb = which ? b - EB : b;
    const int* cnt = which ? g_cnt_u : g_cnt_e;
    int n          = which ? NUSR    : NENT;
    int tbase = tb * TILE;
    int s = 0;
    #pragma unroll
    for (int k = 0; k < 16; k++) {
        int i = tbase + k * 256 + threadIdx.x;
        s += (i < n) ? cnt[i] : 0;
    }
    __shared__ int sh[8];
    int lane = threadIdx.x & 31, wid = threadIdx.x >> 5;
    #pragma unroll
    for (int o = 16; o > 0; o >>= 1) s += __shfl_down_sync(0xffffffffu, s, o);
    if (lane == 0) sh[wid] = s;
    __syncthreads();
    if (threadIdx.x == 0) {
        int t = 0;
        #pragma unroll
        for (int i = 0; i < 8; i++) t += sh[i];
        g_tilesum[b] = t;
    }
}

// Pass B+C merged.
__global__ void k_scanBC() {
    int b = blockIdx.x;
    int which = (b >= EB);
    int tb = which ? b - EB : b;
    const int* cnt = which ? g_cnt_u : g_cnt_e;
    int* off       = which ? g_off_u : g_off_e;
    int* cur       = which ? g_cur_u : g_cur_e;
    int n          = which ? NUSR    : NENT;
    int nb         = which ? UB      : EB;
    int sbase      = which ? EB      : 0;

    __shared__ int s_tileoff;
    if (threadIdx.x < 32) {
        int lane = threadIdx.x;
        int v = (lane < nb) ? g_tilesum[sbase + lane] : 0;
        int x = v;
        #pragma unroll
        for (int o = 1; o < 32; o <<= 1) {
            int y = __shfl_up_sync(0xffffffffu, x, o);
            if (lane >= o) x += y;
        }
        if (lane == tb) s_tileoff = x - v;
    }
    __syncthreads();

    int t = threadIdx.x;
    int lane = t & 31, wid = t >> 5;
    int base = tb * TILE + t * 16;
    int v[16], loc = 0;
    #pragma unroll
    for (int k = 0; k < 16; k++) {
        int i = base + k;
        v[k] = (i < n) ? cnt[i] : 0;
        loc += v[k];
    }
    int x = loc;
    #pragma unroll
    for (int o = 1; o < 32; o <<= 1) {
        int y = __shfl_up_sync(0xffffffffu, x, o);
        if (lane >= o) x += y;
    }
    __shared__ int warpsum[8];
    if (lane == 31) warpsum[wid] = x;
    __syncthreads();
    int wpre = 0;
    #pragma unroll
    for (int i = 0; i < 8; i++) wpre += (i < wid) ? warpsum[i] : 0;
    int excl = s_tileoff + wpre + (x - loc);
    #pragma unroll
    for (int k = 0; k < 16; k++) {
        int i = base + k;
        if (i < n) { off[i] = excl; cur[i] = excl; }
        else if (i == n) { off[n] = excl; }
        excl += v[k];
    }
}

// CSR fill + fp16 conversion of the input entity embedding + zero-invariant
// restoration (no separate cleanup launch).
__global__ void k_fillconv(const int* __restrict__ head, const int* __restrict__ tail,
                           const int* __restrict__ etype,
                           const int* __restrict__ iu, const int* __restrict__ ii,
                           const float* __restrict__ w,
                           const float2* __restrict__ ent_in2) {
    int e = blockIdx.x * blockDim.x + threadIdx.x;
    if (e < ECNT) {
        int h = head[e];
        int pos = atomicAdd(&g_cur_e[h], 1);
        EdgeE ed;
        ed.tail  = tail[e];
        ed.rel   = etype[e] - 1;
        ed.alpha = g_alpha[e];
        ed.eta   = g_eta0[e] / (g_seg_eta[h] + EPSV);
        g_pe[pos] = ed;
    }
    if (e < IECNT) {
        int u = iu[e];
        int pos = atomicAdd(&g_cur_u[u], 1);
        EdgeU eu;
        eu.item = ii[e];
        eu.w    = w[e];
        g_pu[pos] = eu;
    }
    if (e < NENT) { g_cnt_e[e] = 0; g_seg_omega[e] = 0.f; }
    if (e < NUSR) { g_cnt_u[e] = 0; }
    __half2* dst = (__half2*)g_enth[2];
    long total = (long)gridDim.x * blockDim.x;
    const long NH2 = (long)NENT * DD / 2;
    for (long i = e; i < NH2; i += total) {
        dst[i] = __float22half2_rn(ent_in2[i]);
    }
}

// ---------------- fused hop kernel (deferred residual) ------------------------
// One WARP per output row, lane owns 8 channels. hopIdx 0/1: write fp16 state
// only (NO out traffic). hopIdx 2: fused epilogue — out = input + v1 + v2 + v3.
// Entity epilogue reads the fp16 input copy (g_enth[2], 51MB, L2-warm) instead
// of the fp32 input (102MB) — halves the epilogue's input-read traffic.
__global__ void __launch_bounds__(256) k_hop(
                      int hopIdx,
                      const float4* __restrict__ user4,
                      const float4* __restrict__ rel4,
                      float4* __restrict__ outE,
                      float4* __restrict__ outU) {
    const int srcSel = (hopIdx == 0) ? 2 : (hopIdx - 1);
    const __half* srcH = g_enth[srcSel];
    int gw   = (blockIdx.x * blockDim.x + threadIdx.x) >> 5;
    int lane = threadIdx.x & 31;
    if (gw >= NENT + NUSR) return;

    float acc[8];
    #pragma unroll
    for (int k = 0; k < 8; k++) acc[k] = 0.f;

    if (gw < NENT) {
        int row = gw;
        int beg = g_off_e[row], end = g_off_e[row + 1];
        const bool useEta = (hopIdx == 2);
        for (int p = beg; p < end; ++p) {
            EdgeE ed = g_pe[p];
            float rho = useEta ? ed.eta : ed.alpha;
            uint4 hv = ((const uint4*)(srcH + (long)ed.tail * DD))[lane];
            const __half2* hp = (const __half2*)&hv;
            const float4* rp = rel4 + (long)ed.rel * D4 + lane * 2;
            float4 r0 = rp[0], r1 = rp[1];
            float2 f0 = __half22float2(hp[0]);
            float2 f1 = __half22float2(hp[1]);
            float2 f2 = __half22float2(hp[2]);
            float2 f3 = __half22float2(hp[3]);
            acc[0] = fmaf(rho * r0.x, f0.x, acc[0]);
            acc[1] = fmaf(rho * r0.y, f0.y, acc[1]);
            acc[2] = fmaf(rho * r0.z, f1.x, acc[2]);
            acc[3] = fmaf(rho * r0.w, f1.y, acc[3]);
            acc[4] = fmaf(rho * r1.x, f2.x, acc[4]);
            acc[5] = fmaf(rho * r1.y, f2.y, acc[5]);
            acc[6] = fmaf(rho * r1.z, f3.x, acc[6]);
            acc[7] = fmaf(rho * r1.w, f3.y, acc[7]);
        }
        float inv = 1.0f / fmaxf((float)(end - beg), 1.0f);
        float ss = 0.f;
        #pragma unroll
        for (int k = 0; k < 8; k++) { acc[k] *= inv; ss = fmaf(acc[k], acc[k], ss); }
        #pragma unroll
        for (int o = 16; o > 0; o >>= 1) ss += __shfl_xor_sync(0xffffffffu, ss, o);
        float innorm = 1.0f / fmaxf(sqrtf(ss), EPSV);
        float v[8];
        #pragma unroll
        for (int k = 0; k < 8; k++) v[k] = cleanv(acc[k] * innorm);

        if (hopIdx < 2) {
            uint4 hv;
            __half2* hp = (__half2*)&hv;
            hp[0] = __floats2half2_rn(v[0], v[1]);
            hp[1] = __floats2half2_rn(v[2], v[3]);
            hp[2] = __floats2half2_rn(v[4], v[5]);
            hp[3] = __floats2half2_rn(v[6], v[7]);
            ((uint4*)(g_enth[hopIdx] + (long)row * DD))[lane] = hv;
        } else {
            uint4 h0 = ((const uint4*)(g_enth[2] + (long)row * DD))[lane]; // fp16 input
            uint4 h1 = ((const uint4*)(g_enth[0] + (long)row * DD))[lane]; // v1
            uint4 h2 = ((const uint4*)(g_enth[1] + (long)row * DD))[lane]; // v2
            const __half2* p0 = (const __half2*)&h0;
            const __half2* p1 = (const __half2*)&h1;
            const __half2* p2 = (const __half2*)&h2;
            float s[8];
            #pragma unroll
            for (int q = 0; q < 4; q++) {
                float2 a = __half22float2(p0[q]);
                float2 b = __half22float2(p1[q]);
                float2 c = __half22float2(p2[q]);
                s[q * 2]     = a.x + b.x + c.x;
                s[q * 2 + 1] = a.y + b.y + c.y;
            }
            long o0 = (long)row * D4 + lane * 2;
            outE[o0]     = make_float4(s[0] + v[0], s[1] + v[1], s[2] + v[2], s[3] + v[3]);
            outE[o0 + 1] = make_float4(s[4] + v[4], s[5] + v[5], s[6] + v[6], s[7] + v[7]);
        }
    } else {
        int row = gw - NENT;
        int beg = g_off_u[row], end = g_off_u[row + 1];
        for (int p = beg; p < end; ++p) {
            EdgeU eu = g_pu[p];
            float w = eu.w;
            uint4 hv = ((const uint4*)(srcH + (long)eu.item * DD))[lane];
            const __half2* hp = (const __half2*)&hv;
            float2 f0 = __half22float2(hp[0]);
            float2 f1 = __half22float2(hp[1]);
            float2 f2 = __half22float2(hp[2]);
            float2 f3 = __half22float2(hp[3]);
            acc[0] = fmaf(w, f0.x, acc[0]);
            acc[1] = fmaf(w, f0.y, acc[1]);
            acc[2] = fmaf(w, f1.x, acc[2]);
            acc[3] = fmaf(w, f1.y, acc[3]);
            acc[4] = fmaf(w, f2.x, acc[4]);
            acc[5] = fmaf(w, f2.y, acc[5]);
            acc[6] = fmaf(w, f3.x, acc[6]);
            acc[7] = fmaf(w, f3.y, acc[7]);
        }
        float ss = 0.f;
        #pragma unroll
        for (int k = 0; k < 8; k++) ss = fmaf(acc[k], acc[k], ss);
        #pragma unroll
        for (int o = 16; o > 0; o >>= 1) ss += __shfl_xor_sync(0xffffffffu, ss, o);
        float innorm = 1.0f / fmaxf(sqrtf(ss), EPSV);
        float v[8];
        #pragma unroll
        for (int k = 0; k < 8; k++) v[k] = cleanv(acc[k] * innorm);

        if (hopIdx < 2) {
            uint4 hv;
            __half2* hp = (__half2*)&hv;
            hp[0] = __floats2half2_rn(v[0], v[1]);
            hp[1] = __floats2half2_rn(v[2], v[3]);
            hp[2] = __floats2half2_rn(v[4], v[5]);
            hp[3] = __floats2half2_rn(v[6], v[7]);
            ((uint4*)(g_usrh[hopIdx] + (long)row * DD))[lane] = hv;
        } else {
            uint4 h1 = ((const uint4*)(g_usrh[0] + (long)row * DD))[lane];
            uint4 h2 = ((const uint4*)(g_usrh[1] + (long)row * DD))[lane];
            const __half2* p1 = (const __half2*)&h1;
            const __half2* p2 = (const __half2*)&h2;
            float s[8];
            #pragma unroll
            for (int q = 0; q < 4; q++) {
                float2 a = __half22float2(p1[q]);
                float2 b = __half22float2(p2[q]);
                s[q * 2]     = a.x + b.x;
                s[q * 2 + 1] = a.y + b.y;
            }
            long o0 = (long)row * D4 + lane * 2;
            float4 b0 = user4[o0];
            float4 b1 = user4[o0 + 1];
            outU[o0]     = make_float4(b0.x + s[0] + v[0], b0.y + s[1] + v[1],
                                       b0.z + s[2] + v[2], b0.w + s[3] + v[3]);
            outU[o0 + 1] = make_float4(b1.x + s[4] + v[4], b1.y + s[5] + v[5],
                                       b1.z + s[6] + v[6], b1.w + s[7] + v[7]);
        }
    }
}

// ---------------- launch ------------------------------------------------------
extern "C" void kernel_launch(void* const* d_in, const int* in_sizes, int n_in,
                              void* d_out, int out_size) {
    const float* user_emb   = (const float*)d_in[0];
    const float* entity_emb = (const float*)d_in[1];
    const int*   edge_index = (const int*)d_in[2];   // [2, E]
    const int*   edge_type  = (const int*)d_in[3];
    const float* omega      = (const float*)d_in[4];
    const int*   inter_edge = (const int*)d_in[5];   // [2, IE]
    const float* inter_w    = (const float*)d_in[6];
    const float* rel_emb    = (const float*)d_in[7];
    float* out = (float*)d_out;

    const int* head = edge_index;
    const int* tail = edge_index + ECNT;
    const int* iu   = inter_edge;
    const int* ii   = inter_edge + IECNT;

    const float4* usr_in = (const float4*)user_emb;
    const float4* rel4   = (const float4*)rel_emb;
    float4* outE = (float4*)out;
    float4* outU = (float4*)(out + (long)NENT * DD);

    const int T = 256;
    const int EG = (ECNT + T - 1) / T;
    k_count   <<<EG, T>>>(head, omega, iu);                           // 0
    k_alpha   <<<EG, T>>>(head, omega);                               // 1
    k_scanA   <<<EB + UB, T>>>();                                     // 2
    k_scanBC  <<<EB + UB, T>>>();                                     // 3
    k_fillconv<<<EG, T>>>(head, tail, edge_type, iu, ii, inter_w,
                          (const float2*)entity_emb);                 // 4

    const int G = ((NENT + NUSR) * 32 + T - 1) / T;   // one warp per row
    k_hop<<<G, T>>>(0, usr_in, rel4, outE, outU);                     // 5 (profiled)
    k_hop<<<G, T>>>(1, usr_in, rel4, outE, outU);
    k_hop<<<G, T>>>(2, usr_in, rel4, outE, outU);
}